// round 16
// baseline (speedup 1.0000x reference)
#include <cuda_runtime.h>
#include <cuda_fp16.h>
#include <cstdint>
#include <cstddef>

#define N_NODES 50000
#define N_PADR  50048
#define N_EDGES_MAX 800000
#define D_V 133
#define D_E 14
#define D_H 300
#define GN  300
#define KP_V 160               // D_V padded to mult of 32
#define KP_H 320               // D_H padded to mult of 32
#define KH2 320                // half-precision H row pitch (elements)
#define NPADW 384              // weight rows padded (>= 5*64)

// ---------------- scratch (static device globals; no allocation) ------------
__device__ __align__(256) float g_Cs[(size_t)N_NODES * D_H];
__device__ __align__(256) float g_Ps[(size_t)N_NODES * D_H];
__device__ __align__(256) float g_SE[(size_t)N_NODES * D_E];
__device__ __align__(256) __half g_Hh[(size_t)N_PADR * KH2];   // fp16 H for gather
__device__ __align__(256) float g_A [(size_t)N_PADR * KP_H];   // tf32-rounded
__device__ __align__(256) float g_V [(size_t)N_PADR * KP_V];   // tf32-rounded
__device__ __align__(256) float g_Wi [NPADW * KP_V];
__device__ __align__(256) float g_WoV[NPADW * KP_V];
__device__ __align__(256) float g_WhH[NPADW * KP_H];
__device__ __align__(256) float g_WoH[NPADW * KP_H];
__device__ int   g_deg[N_NODES];
__device__ int   g_cnt[N_NODES];
__device__ int   g_rowptr[N_NODES + 1];
__device__ int   g_srcA[N_EDGES_MAX];
__device__ int   g_dstA[N_EDGES_MAX];
__device__ int   g_csr[N_EDGES_MAX];
__device__ int   g_blk[256];
__device__ int   g_blkoff[256];
__device__ int   g_is64;

// ======================= PTX helpers (family-safe only) =====================
__device__ __forceinline__ uint32_t s2u(const void* p) {
    uint32_t a;
    asm("{ .reg .u64 t; cvta.to.shared.u64 t, %1; cvt.u32.u64 %0, t; }"
        : "=r"(a) : "l"(p));
    return a;
}
__device__ __forceinline__ float tf32r(float x) {
    uint32_t u;
    asm("cvt.rna.tf32.f32 %0, %1;" : "=r"(u) : "f"(x));
    return __uint_as_float(u);
}
#define CPA16(sa, ga) \
    asm volatile("cp.async.cg.shared.global [%0], [%1], 16;" :: "r"(sa), "l"(ga) : "memory")
#define CP_COMMIT() asm volatile("cp.async.commit_group;" ::: "memory")
template <int N>
__device__ __forceinline__ void cp_wait() {
    asm volatile("cp.async.wait_group %0;" :: "n"(N) : "memory");
}
#define LDSM_X4(r0, r1, r2, r3, addr) \
    asm volatile("ldmatrix.sync.aligned.m8n8.x4.shared.b16 {%0,%1,%2,%3}, [%4];" \
        : "=r"(r0), "=r"(r1), "=r"(r2), "=r"(r3) : "r"(addr))
// tf32 m16n8k8: A 4 regs, B 2 regs, fp32 acc
#define MMATF32(d, a0, a1, a2, a3, b0, b1) \
    asm volatile("mma.sync.aligned.m16n8k8.row.col.f32.tf32.tf32.f32 " \
        "{%0,%1,%2,%3}, {%4,%5,%6,%7}, {%8,%9}, {%0,%1,%2,%3};" \
        : "+f"((d)[0]), "+f"((d)[1]), "+f"((d)[2]), "+f"((d)[3]) \
        : "r"(a0), "r"(a1), "r"(a2), "r"(a3), "r"(b0), "r"(b1))

// fp32 rows: 32-K chunk = 128B/row, pitch 144B (conflict-free ldmatrix)
#define ROWB   144
#define STAGE_B (192 * ROWB)       // 27648
#define TG_SMEM (2 * STAGE_B)      // 55296; 3 CTAs/SM in 228KB smem
#define B_OFF  (128 * ROWB)

// ======================= setup kernels ======================================
__global__ void init_k(const unsigned long long* __restrict__ p, int n64) {
    int i = blockIdx.x * blockDim.x + threadIdx.x;
    if (i == 0) {
        int is64 = 1;
        int lim = n64 < 64 ? n64 : 64;
        for (int j = 0; j < lim; j++)
            if (p[j] >= (1ULL << 32)) { is64 = 0; break; }
        g_is64 = is64;
    }
    if (i < N_NODES) { g_deg[i] = 0; g_cnt[i] = 0; }
    if (i < N_NODES * D_E) g_SE[i] = 0.f;
}

__global__ void convert_hist_k(const void* __restrict__ ei, int nE) {
    int e = blockIdx.x * blockDim.x + threadIdx.x;
    if (e >= nE) return;
    int s, d;
    if (g_is64) {
        const long long* p = (const long long*)ei;
        s = (int)p[e]; d = (int)p[nE + e];
    } else {
        const int* p = (const int*)ei;
        s = p[e]; d = p[nE + e];
    }
    g_srcA[e] = s;
    g_dstA[e] = d;
    atomicAdd(&g_deg[d], 1);
}

__global__ void scan1_k() {
    __shared__ int sm[256];
    int t = threadIdx.x, b = blockIdx.x;
    int i = b * 256 + t;
    sm[t] = (i < N_NODES) ? g_deg[i] : 0;
    __syncthreads();
    for (int off = 128; off; off >>= 1) {
        if (t < off) sm[t] += sm[t + off];
        __syncthreads();
    }
    if (t == 0) g_blk[b] = sm[0];
}
__global__ void scan2_k(int nb) {
    __shared__ int sm[256];
    int t = threadIdx.x;
    int v = (t < nb) ? g_blk[t] : 0;
    sm[t] = v;
    __syncthreads();
    for (int off = 1; off < 256; off <<= 1) {
        int u = (t >= off) ? sm[t - off] : 0;
        __syncthreads();
        sm[t] += u;
        __syncthreads();
    }
    if (t < nb) g_blkoff[t] = sm[t] - v;
}
__global__ void scan3_k() {
    __shared__ int sm[256];
    int t = threadIdx.x, b = blockIdx.x;
    int i = b * 256 + t;
    int v = (i < N_NODES) ? g_deg[i] : 0;
    sm[t] = v;
    __syncthreads();
    for (int off = 1; off < 256; off <<= 1) {
        int u = (t >= off) ? sm[t - off] : 0;
        __syncthreads();
        sm[t] += u;
        __syncthreads();
    }
    int excl = sm[t] - v + g_blkoff[b];
    if (i < N_NODES) g_rowptr[i] = excl;
    if (i == N_NODES - 1) g_rowptr[N_NODES] = excl + v;
}

__global__ void csr_fill_k(int nE) {
    int e = blockIdx.x * blockDim.x + threadIdx.x;
    if (e >= nE) return;
    int d = g_dstA[e];
    int pos = atomicAdd(&g_cnt[d], 1);
    g_csr[g_rowptr[d] + pos] = g_srcA[e];
}

__global__ void se_scatter_k(const float* __restrict__ E, int nE) {
    int e = blockIdx.x * blockDim.x + threadIdx.x;
    if (e >= nE) return;
    int d = g_dstA[e];
    float* base = &g_SE[(size_t)d * D_E];
    const float* src = &E[(size_t)e * D_E];
#pragma unroll
    for (int k = 0; k < D_E; k++) atomicAdd(base + k, src[k]);
}

// ======================= tf32 prep kernels ==================================
__global__ void roundV_k(const float* __restrict__ V, int M) {
    int idx4 = blockIdx.x * blockDim.x + threadIdx.x;
    if (idx4 >= M * (KP_V / 4)) return;
    int m = idx4 / (KP_V / 4);
    int k0 = (idx4 - m * (KP_V / 4)) * 4;
    const float* row = V + (size_t)m * D_V;
    float4 v;
    v.x = (k0     < D_V) ? tf32r(row[k0])     : 0.f;
    v.y = (k0 + 1 < D_V) ? tf32r(row[k0 + 1]) : 0.f;
    v.z = (k0 + 2 < D_V) ? tf32r(row[k0 + 2]) : 0.f;
    v.w = (k0 + 3 < D_V) ? tf32r(row[k0 + 3]) : 0.f;
    ((float4*)g_V)[idx4] = v;
}

__global__ void prepW_k(const float* __restrict__ W, int ldW, int colOff, int K,
                        int Kpad, float* __restrict__ out) {
    int idx = blockIdx.x * blockDim.x + threadIdx.x;
    if (idx >= NPADW * Kpad) return;
    int n = idx / Kpad, k = idx - n * Kpad;
    out[idx] = (n < GN && k < K) ? tf32r(W[(size_t)n * ldW + colOff + k]) : 0.f;
}

// ------- gather + segment-sum over fp16 H rows, emits tf32 fp32 A ----------
// Lane-balanced: 4-edge groups give each lane 5 loads (4 main + 1 distributed
// hi part); hi partials reduced across lanes with shfl_xor at the end.
__device__ __forceinline__ void acc8(float* a, uint4 u) {
    float2 f;
    f = __half22float2(*(__half2*)&u.x); a[0] += f.x; a[1] += f.y;
    f = __half22float2(*(__half2*)&u.y); a[2] += f.x; a[3] += f.y;
    f = __half22float2(*(__half2*)&u.z); a[4] += f.x; a[5] += f.y;
    f = __half22float2(*(__half2*)&u.w); a[6] += f.x; a[7] += f.y;
}
__device__ __forceinline__ float4 roundq(const float* a) {
    float4 r;
    r.x = tf32r(a[0]); r.y = tf32r(a[1]); r.z = tf32r(a[2]); r.w = tf32r(a[3]);
    return r;
}

__global__ __launch_bounds__(256) void seg_sum_k() {
    int gw = (blockIdx.x * blockDim.x + threadIdx.x) >> 5;
    int lane = threadIdx.x & 31;
    if (gw >= N_NODES) return;
    int beg = g_rowptr[gw], end = g_rowptr[gw + 1];
    float a0[8] = {}, a1[8] = {};
    int eh = lane >> 3;                 // edge-in-group for hi load
    int oh = 32 + (lane & 7);           // hi uint4 offset (cols 256..319)

    int i = beg;
    for (; i + 3 < end; i += 4) {
        const uint4* r0 = (const uint4*)(g_Hh + (size_t)g_csr[i]      * KH2);
        const uint4* r1 = (const uint4*)(g_Hh + (size_t)g_csr[i + 1]  * KH2);
        const uint4* r2 = (const uint4*)(g_Hh + (size_t)g_csr[i + 2]  * KH2);
        const uint4* r3 = (const uint4*)(g_Hh + (size_t)g_csr[i + 3]  * KH2);
        const uint4* rh = (const uint4*)(g_Hh + (size_t)g_csr[i + eh] * KH2);
        uint4 x0 = __ldg(&r0[lane]), x1 = __ldg(&r1[lane]);
        uint4 x2 = __ldg(&r2[lane]), x3 = __ldg(&r3[lane]);
        uint4 y  = __ldg(&rh[oh]);
        acc8(a0, x0); acc8(a0, x1); acc8(a0, x2); acc8(a0, x3);
        acc8(a1, y);
    }
    for (; i < end; i++) {
        const uint4* r0 = (const uint4*)(g_Hh + (size_t)g_csr[i] * KH2);
        uint4 x0 = __ldg(&r0[lane]);
        if (lane < 8) { uint4 x1 = __ldg(&r0[32 + lane]); acc8(a1, x1); }
        acc8(a0, x0);
    }

    // hi partials for column block (lane&7) live in lanes {k, k+8, k+16, k+24}
#pragma unroll
    for (int o = 8; o <= 16; o <<= 1)
#pragma unroll
        for (int j = 0; j < 8; j++)
            a1[j] += __shfl_xor_sync(0xffffffffu, a1[j], o);

    float4* Av = (float4*)(g_A + (size_t)gw * KP_H);
    Av[lane * 2]     = roundq(a0);
    Av[lane * 2 + 1] = roundq(a0 + 4);
    if (lane < 8) {
        Av[64 + lane * 2]     = roundq(a1);
        Av[64 + lane * 2 + 1] = roundq(a1 + 4);
    }
}

// ==== SIMT SGEMM (Cs, K=14) with fused fp16-H0 add -> Rs ====================
__global__ __launch_bounds__(256) void sgemm_k(
    const float* __restrict__ X, int K, int M,
    const float* __restrict__ W, int ldW, int colOff,
    const float* __restrict__ bias, const int* __restrict__ degv,
    const __half* __restrict__ addh, float* __restrict__ Out)
{
    __shared__ __align__(16) float As[8][128];
    __shared__ __align__(16) float Bs[8][128];
    int tid = threadIdx.x;
    int m0 = blockIdx.x * 128;
    int n0 = blockIdx.y * 128;
    int xr = tid >> 3, xc = tid & 7;
    int tx = tid & 15, ty = tid >> 4;
    int mA = ty * 4, mB = 64 + ty * 4;
    int nA = tx * 4, nB = 64 + tx * 4;
    float acc[8][8] = {};

    for (int k0 = 0; k0 < K; k0 += 8) {
#pragma unroll
        for (int i = 0; i < 4; i++) {
            int m = xr + i * 32;
            int gm = m0 + m, gk = k0 + xc;
            As[xc][m] = (gm < M && gk < K) ? X[(size_t)gm * K + gk] : 0.f;
        }
#pragma unroll
        for (int i = 0; i < 4; i++) {
            int n = xr + i * 32;
            int gn = n0 + n, gk = k0 + xc;
            Bs[xc][n] = (gn < GN && gk < K) ? W[(size_t)gn * ldW + colOff + gk] : 0.f;
        }
        __syncthreads();
#pragma unroll
        for (int k = 0; k < 8; k++) {
            float4 q0 = *(const float4*)&As[k][mA];
            float4 q1 = *(const float4*)&As[k][mB];
            float4 b0 = *(const float4*)&Bs[k][nA];
            float4 b1 = *(const float4*)&Bs[k][nB];
            float av[8] = {q0.x, q0.y, q0.z, q0.w, q1.x, q1.y, q1.z, q1.w};
            float bv[8] = {b0.x, b0.y, b0.z, b0.w, b1.x, b1.y, b1.z, b1.w};
#pragma unroll
            for (int i = 0; i < 8; i++)
#pragma unroll
                for (int j = 0; j < 8; j++)
                    acc[i][j] += av[i] * bv[j];
        }
        __syncthreads();
    }
#pragma unroll
    for (int i = 0; i < 8; i++) {
        int m = m0 + ((i < 4) ? (ty * 4 + i) : (64 + ty * 4 + (i - 4)));
        if (m >= M) continue;
        float degf = degv ? (float)degv[m] : 1.f;
#pragma unroll
        for (int j = 0; j < 8; j++) {
            int n = n0 + ((j < 4) ? (tx * 4 + j) : (64 + tx * 4 + (j - 4)));
            if (n >= GN) continue;
            float v = acc[i][j] + degf * bias[n];
            if (addh) v += __half2float(addh[(size_t)m * KH2 + n]);
            Out[(size_t)m * GN + n] = v;
        }
    }
}

// ========== TF32 HMMA GEMM: 128x64 tile, 3 CTAs/SM, 1 product/K ============
// Outputs: Out (f32, GN pitch) and/or OutH (fp16, KH2 pitch). Vector epilogue.
__global__ void __launch_bounds__(256, 3) tgemm_k(
    const float* __restrict__ X, const float* __restrict__ W,
    int Kpad, int nchunks, int M,
    const float* __restrict__ bias, const float* __restrict__ add1,
    const float* __restrict__ add2, int relu,
    float* __restrict__ Out, __half* __restrict__ OutH)
{
    extern __shared__ __align__(16) char smem[];
    uint32_t sb = s2u(smem);
    int tid = threadIdx.x, wid = tid >> 5, lane = tid & 31;
    int wm = wid & 3, wn = wid >> 2;       // 4 x 2 warp grid, warp tile 32x32
    int m0 = blockIdx.x * 128, n0 = blockIdx.y * 64;

    size_t ldb = (size_t)Kpad * 4;
    const char* gptr[2];
    gptr[0] = (const char*)(X + (size_t)m0 * Kpad);
    gptr[1] = (const char*)(W + (size_t)n0 * Kpad);

    float acc[2][4][4] = {};

#define LOAD_STAGE(s, c)                                                       \
    do {                                                                       \
        uint32_t _base = sb + (uint32_t)(s) * STAGE_B;                         \
        _Pragma("unroll")                                                      \
        for (int _t = 0; _t < 6; _t++) {                                       \
            int _id = _t * 256 + tid;                                          \
            int _r = _id >> 3;               /* 0..191 */                      \
            int _q = _id & 7;                                                  \
            int _mat = _r >> 7;              /* 0=A, 1=B */                    \
            int _rl = _r & 127;                                                \
            uint32_t _so = _base + _r * ROWB + _q * 16;                        \
            const char* _g = gptr[_mat] + (size_t)_rl * ldb                    \
                             + (size_t)(c) * 128 + _q * 16;                    \
            CPA16(_so, _g);                                                    \
        }                                                                      \
    } while (0)

    LOAD_STAGE(0, 0);
    CP_COMMIT();

    int r8 = lane & 7, qd = lane >> 3;
    int qrow = ((qd >> 1) << 3) + r8;
    int qoff = qrow * ROWB + ((qd & 1) << 4);

    for (int i = 0; i < nchunks; i++) {
        if (i + 1 < nchunks) {
            LOAD_STAGE((i + 1) & 1, i + 1);
            CP_COMMIT();
            cp_wait<1>();
        } else {
            cp_wait<0>();
        }
        __syncthreads();
        uint32_t stb = sb + (uint32_t)(i & 1) * STAGE_B;
        uint32_t abase = stb + (wm * 32) * ROWB + qoff;
        uint32_t bbase = stb + B_OFF + (wn * 32) * ROWB + qoff;

#pragma unroll
        for (int ks = 0; ks < 4; ks++) {       // four 8-K sub-chunks
            uint32_t a[2][4], b[4][2];
#pragma unroll
            for (int mt = 0; mt < 2; mt++) {
                uint32_t r0, r1, r2, r3;
                LDSM_X4(r0, r1, r2, r3, abase + mt * 16 * ROWB + ks * 32);
                a[mt][0] = r0; a[mt][1] = r2;
                a[mt][2] = r1; a[mt][3] = r3;
            }
#pragma unroll
            for (int p = 0; p < 2; p++) {
                uint32_t r0, r1, r2, r3;
                LDSM_X4(r0, r1, r2, r3, bbase + p * 16 * ROWB + ks * 32);
                b[p * 2][0] = r0;     b[p * 2][1] = r1;
                b[p * 2 + 1][0] = r2; b[p * 2 + 1][1] = r3;
            }
#pragma unroll
            for (int mt = 0; mt < 2; mt++)
#pragma unroll
                for (int nt = 0; nt < 4; nt++)
                    MMATF32(acc[mt][nt], a[mt][0], a[mt][1], a[mt][2], a[mt][3],
                            b[nt][0], b[nt][1]);
        }
        __syncthreads();
    }
#undef LOAD_STAGE

    float* Ds = (float*)smem;          // 128 x 68 floats = 34816 B < TG_SMEM
    int g = lane >> 2, tg = lane & 3;
#pragma unroll
    for (int mt = 0; mt < 2; mt++)
#pragma unroll
        for (int nt = 0; nt < 4; nt++) {
            int row = wm * 32 + mt * 16 + g;
            int col = wn * 32 + nt * 8 + tg * 2;
            Ds[row * 68 + col]           = acc[mt][nt][0];
            Ds[row * 68 + col + 1]       = acc[mt][nt][1];
            Ds[(row + 8) * 68 + col]     = acc[mt][nt][2];
            Ds[(row + 8) * 68 + col + 1] = acc[mt][nt][3];
        }
    __syncthreads();

    // vector epilogue: 2 cols x 16 rows per thread (all 2-elem accesses aligned)
    int c2 = (tid & 31) * 2, rg = tid >> 5;
    int n = n0 + c2;
    bool nv = n < GN;                      // n even, GN even -> pairwise valid
    float bx = 0.f, by = 0.f;
    if (bias && nv) { bx = bias[n]; by = bias[n + 1]; }
    for (int r = rg * 16; r < rg * 16 + 16; r++) {
        int gm = m0 + r;
        if (gm >= M) break;
        float2 v = *(float2*)&Ds[r * 68 + c2];
        if (nv) {
            v.x += bx; v.y += by;
            if (add1) {
                float2 t = *(const float2*)&add1[(size_t)gm * GN + n];
                v.x += t.x; v.y += t.y;
            }
            if (add2) {
                float2 t = *(const float2*)&add2[(size_t)gm * GN + n];
                v.x += t.x; v.y += t.y;
            }
            if (relu) { v.x = fmaxf(v.x, 0.f); v.y = fmaxf(v.y, 0.f); }
            if (Out) *(float2*)&Out[(size_t)gm * GN + n] = v;
        } else {
            v.x = 0.f; v.y = 0.f;
        }
        if (OutH)
            *(__half2*)&OutH[(size_t)gm * KH2 + n] = __floats2half2_rn(v.x, v.y);
    }
}

// ======================= host orchestration =================================
extern "C" void kernel_launch(void* const* d_in, const int* in_sizes, int n_in,
                              void* d_out, int out_size) {
    const float* V   = (const float*)d_in[0];
    const float* E   = (const float*)d_in[1];
    const void*  EI  = d_in[2];
    const float* W_i = (const float*)d_in[3];
    const float* b_i = (const float*)d_in[4];
    const float* W_h = (const float*)d_in[5];
    const float* b_h = (const float*)d_in[6];
    const float* W_o = (const float*)d_in[7];
    const float* b_o = (const float*)d_in[8];
    float* out = (float*)d_out;

    int nE = in_sizes[2] / 2;
    int M  = in_sizes[0] / D_V;   // 50000

    float *Cs, *Ps, *SE, *A, *Vr;
    float *Wi, *WoV, *WhH, *WoH;
    __half* Hh;
    int *deg;
    cudaGetSymbolAddress((void**)&Cs, g_Cs);
    cudaGetSymbolAddress((void**)&Ps, g_Ps);
    cudaGetSymbolAddress((void**)&SE, g_SE);
    cudaGetSymbolAddress((void**)&Hh, g_Hh);
    cudaGetSymbolAddress((void**)&A,  g_A);
    cudaGetSymbolAddress((void**)&Vr, g_V);
    cudaGetSymbolAddress((void**)&Wi, g_Wi);
    cudaGetSymbolAddress((void**)&WoV, g_WoV);
    cudaGetSymbolAddress((void**)&WhH, g_WhH);
    cudaGetSymbolAddress((void**)&WoH, g_WoH);
    cudaGetSymbolAddress((void**)&deg, g_deg);

    cudaFuncSetAttribute(tgemm_k, cudaFuncAttributeMaxDynamicSharedMemorySize, TG_SMEM);

    cudaStream_t st = 0;
    const int TB = 256;
    int zeroN = N_NODES * D_E;
    int NB = (N_NODES + 255) / 256;
    dim3 tgGrid((M + 127) / 128, 5);       // 5 x 64 = 320 cols
    dim3 gemmGrid((M + 127) / 128, 3);
    int segGrid = (N_NODES * 32 + TB - 1) / TB;

    // ---- launches 1-4: keep tgemm_k at position 4 for ncu visibility -------
    roundV_k<<<(M * (KP_V / 4) + TB - 1) / TB, TB, 0, st>>>(V, M);             // 1
    prepW_k<<<(NPADW * KP_V + TB - 1) / TB, TB, 0, st>>>(W_i, D_V, 0, D_V,
                                                          KP_V, Wi);          // 2
    prepW_k<<<(NPADW * KP_H + TB - 1) / TB, TB, 0, st>>>(W_h, D_H + D_E, 0, D_H,
                                                          KP_H, WhH);         // 3
    // H0 = relu(V W_i^T + b_i): fp16 only
    tgemm_k<<<tgGrid, 256, TG_SMEM, st>>>(Vr, Wi, KP_V, KP_V / 32, M,
                                          b_i, nullptr, nullptr, 1,
                                          nullptr, Hh);                       // 4 (profiled)

    // ---- remaining prep + graph build --------------------------------------
    prepW_k<<<(NPADW * KP_V + TB - 1) / TB, TB, 0, st>>>(W_o, D_V + D_H, 0, D_V,
                                                          KP_V, WoV);
    prepW_k<<<(NPADW * KP_H + TB - 1) / TB, TB, 0, st>>>(W_o, D_V + D_H, D_V, D_H,
                                                          KP_H, WoH);
    init_k<<<(zeroN + TB - 1) / TB, TB, 0, st>>>((const unsigned long long*)EI, nE);
    convert_hist_k<<<(nE + TB - 1) / TB, TB, 0, st>>>(EI, nE);
    scan1_k<<<NB, 256, 0, st>>>();
    scan2_k<<<1, 256, 0, st>>>(NB);
    scan3_k<<<NB, 256, 0, st>>>();
    csr_fill_k<<<(nE + TB - 1) / TB, TB, 0, st>>>(nE);
    se_scatter_k<<<(nE + TB - 1) / TB, TB, 0, st>>>(E, nE);

    // Ps = V @ W_oV^T + b_o
    tgemm_k<<<tgGrid, 256, TG_SMEM, st>>>(Vr, WoV, KP_V, KP_V / 32, M,
                                          b_o, nullptr, nullptr, 0, Ps, nullptr);
    // Rs (in Cs) = SE @ W_hE^T + deg * b_h + H0(fp16)   (SIMT, K=14)
    sgemm_k<<<gemmGrid, TB, 0, st>>>(SE, D_E, M, W_h, D_H + D_E, D_H, b_h, deg, Hh, Cs);

    // layer 1: Hh = fp16(relu(segsum(Hh[src]) @ W_hH^T + Rs))
    seg_sum_k<<<segGrid, TB, 0, st>>>();
    tgemm_k<<<tgGrid, 256, TG_SMEM, st>>>(A, WhH, KP_H, KP_H / 32, M,
                                          nullptr, Cs, nullptr, 1, nullptr, Hh);
    // layer 2
    seg_sum_k<<<segGrid, TB, 0, st>>>();
    tgemm_k<<<tgGrid, 256, TG_SMEM, st>>>(A, WhH, KP_H, KP_H / 32, M,
                                          nullptr, Cs, nullptr, 1, nullptr, Hh);
    // final: out = relu(Ps + segsum(Hh[src]) @ W_oH^T)
    seg_sum_k<<<segGrid, TB, 0, st>>>();
    tgemm_k<<<tgGrid, 256, TG_SMEM, st>>>(A, WoH, KP_H, KP_H / 32, M,
                                          nullptr, Ps, nullptr, 1, out, nullptr);
}

// round 17
// speedup vs baseline: 1.1616x; 1.1616x over previous
#include <cuda_runtime.h>
#include <cuda_fp16.h>
#include <cstdint>
#include <cstddef>

#define N_NODES 50000
#define N_PADR  50048
#define N_EDGES_MAX 800000
#define D_V 133
#define D_E 14
#define D_H 300
#define GN  300
#define KP_V 160               // D_V padded to mult of 32
#define KP_H 320               // D_H padded to mult of 32
#define KH2 320                // half-precision H row pitch (elements)
#define NPADW 384              // weight rows padded (>= 5*64)

// ---------------- scratch (static device globals; no allocation) ------------
__device__ __align__(256) float g_Cs[(size_t)N_NODES * D_H];
__device__ __align__(256) float g_Ps[(size_t)N_NODES * D_H];
__device__ __align__(256) float g_SE[(size_t)N_NODES * D_E];
__device__ __align__(256) __half g_Hh[(size_t)N_PADR * KH2];   // fp16 H for gather
__device__ __align__(256) float g_A [(size_t)N_PADR * KP_H];   // tf32-rounded
__device__ __align__(256) float g_V [(size_t)N_PADR * KP_V];   // tf32-rounded
__device__ __align__(256) float g_Wi [NPADW * KP_V];
__device__ __align__(256) float g_WoV[NPADW * KP_V];
__device__ __align__(256) float g_WhH[NPADW * KP_H];
__device__ __align__(256) float g_WoH[NPADW * KP_H];
__device__ int   g_deg[N_NODES];
__device__ int   g_cnt[N_NODES];
__device__ int   g_rowptr[N_NODES + 1];
__device__ int   g_srcA[N_EDGES_MAX];
__device__ int   g_dstA[N_EDGES_MAX];
__device__ int   g_csr[N_EDGES_MAX];
__device__ int   g_blk[256];
__device__ int   g_blkoff[256];
__device__ int   g_is64;

// ======================= PTX helpers (family-safe only) =====================
__device__ __forceinline__ uint32_t s2u(const void* p) {
    uint32_t a;
    asm("{ .reg .u64 t; cvta.to.shared.u64 t, %1; cvt.u32.u64 %0, t; }"
        : "=r"(a) : "l"(p));
    return a;
}
__device__ __forceinline__ float tf32r(float x) {
    uint32_t u;
    asm("cvt.rna.tf32.f32 %0, %1;" : "=r"(u) : "f"(x));
    return __uint_as_float(u);
}
#define CPA16(sa, ga) \
    asm volatile("cp.async.cg.shared.global [%0], [%1], 16;" :: "r"(sa), "l"(ga) : "memory")
#define CP_COMMIT() asm volatile("cp.async.commit_group;" ::: "memory")
template <int N>
__device__ __forceinline__ void cp_wait() {
    asm volatile("cp.async.wait_group %0;" :: "n"(N) : "memory");
}
#define LDSM_X4(r0, r1, r2, r3, addr) \
    asm volatile("ldmatrix.sync.aligned.m8n8.x4.shared.b16 {%0,%1,%2,%3}, [%4];" \
        : "=r"(r0), "=r"(r1), "=r"(r2), "=r"(r3) : "r"(addr))
// tf32 m16n8k8: A 4 regs, B 2 regs, fp32 acc
#define MMATF32(d, a0, a1, a2, a3, b0, b1) \
    asm volatile("mma.sync.aligned.m16n8k8.row.col.f32.tf32.tf32.f32 " \
        "{%0,%1,%2,%3}, {%4,%5,%6,%7}, {%8,%9}, {%0,%1,%2,%3};" \
        : "+f"((d)[0]), "+f"((d)[1]), "+f"((d)[2]), "+f"((d)[3]) \
        : "r"(a0), "r"(a1), "r"(a2), "r"(a3), "r"(b0), "r"(b1))

// fp32 rows: 32-K chunk = 128B/row, pitch 144B (conflict-free ldmatrix)
#define ROWB   144
#define STAGE_B (192 * ROWB)       // 27648
#define TG_SMEM (2 * STAGE_B)      // 55296; 3 CTAs/SM in 228KB smem
#define B_OFF  (128 * ROWB)

// ======================= setup kernels ======================================
__global__ void init_k(const unsigned long long* __restrict__ p, int n64) {
    int i = blockIdx.x * blockDim.x + threadIdx.x;
    if (i == 0) {
        int is64 = 1;
        int lim = n64 < 64 ? n64 : 64;
        for (int j = 0; j < lim; j++)
            if (p[j] >= (1ULL << 32)) { is64 = 0; break; }
        g_is64 = is64;
    }
    if (i < N_NODES) { g_deg[i] = 0; g_cnt[i] = 0; }
    if (i < N_NODES * D_E) g_SE[i] = 0.f;
}

__global__ void convert_hist_k(const void* __restrict__ ei, int nE) {
    int e = blockIdx.x * blockDim.x + threadIdx.x;
    if (e >= nE) return;
    int s, d;
    if (g_is64) {
        const long long* p = (const long long*)ei;
        s = (int)p[e]; d = (int)p[nE + e];
    } else {
        const int* p = (const int*)ei;
        s = p[e]; d = p[nE + e];
    }
    g_srcA[e] = s;
    g_dstA[e] = d;
    atomicAdd(&g_deg[d], 1);
}

__global__ void scan1_k() {
    __shared__ int sm[256];
    int t = threadIdx.x, b = blockIdx.x;
    int i = b * 256 + t;
    sm[t] = (i < N_NODES) ? g_deg[i] : 0;
    __syncthreads();
    for (int off = 128; off; off >>= 1) {
        if (t < off) sm[t] += sm[t + off];
        __syncthreads();
    }
    if (t == 0) g_blk[b] = sm[0];
}
__global__ void scan2_k(int nb) {
    __shared__ int sm[256];
    int t = threadIdx.x;
    int v = (t < nb) ? g_blk[t] : 0;
    sm[t] = v;
    __syncthreads();
    for (int off = 1; off < 256; off <<= 1) {
        int u = (t >= off) ? sm[t - off] : 0;
        __syncthreads();
        sm[t] += u;
        __syncthreads();
    }
    if (t < nb) g_blkoff[t] = sm[t] - v;
}
__global__ void scan3_k() {
    __shared__ int sm[256];
    int t = threadIdx.x, b = blockIdx.x;
    int i = b * 256 + t;
    int v = (i < N_NODES) ? g_deg[i] : 0;
    sm[t] = v;
    __syncthreads();
    for (int off = 1; off < 256; off <<= 1) {
        int u = (t >= off) ? sm[t - off] : 0;
        __syncthreads();
        sm[t] += u;
        __syncthreads();
    }
    int excl = sm[t] - v + g_blkoff[b];
    if (i < N_NODES) g_rowptr[i] = excl;
    if (i == N_NODES - 1) g_rowptr[N_NODES] = excl + v;
}

__global__ void csr_fill_k(int nE) {
    int e = blockIdx.x * blockDim.x + threadIdx.x;
    if (e >= nE) return;
    int d = g_dstA[e];
    int pos = atomicAdd(&g_cnt[d], 1);
    g_csr[g_rowptr[d] + pos] = g_srcA[e];
}

__global__ void se_scatter_k(const float* __restrict__ E, int nE) {
    int e = blockIdx.x * blockDim.x + threadIdx.x;
    if (e >= nE) return;
    int d = g_dstA[e];
    float* base = &g_SE[(size_t)d * D_E];
    const float* src = &E[(size_t)e * D_E];
#pragma unroll
    for (int k = 0; k < D_E; k++) atomicAdd(base + k, src[k]);
}

// ======================= tf32 prep kernels ==================================
__global__ void roundV_k(const float* __restrict__ V, int M) {
    int idx4 = blockIdx.x * blockDim.x + threadIdx.x;
    if (idx4 >= M * (KP_V / 4)) return;
    int m = idx4 / (KP_V / 4);
    int k0 = (idx4 - m * (KP_V / 4)) * 4;
    const float* row = V + (size_t)m * D_V;
    float4 v;
    v.x = (k0     < D_V) ? tf32r(row[k0])     : 0.f;
    v.y = (k0 + 1 < D_V) ? tf32r(row[k0 + 1]) : 0.f;
    v.z = (k0 + 2 < D_V) ? tf32r(row[k0 + 2]) : 0.f;
    v.w = (k0 + 3 < D_V) ? tf32r(row[k0 + 3]) : 0.f;
    ((float4*)g_V)[idx4] = v;
}

__global__ void prepW_k(const float* __restrict__ W, int ldW, int colOff, int K,
                        int Kpad, float* __restrict__ out) {
    int idx = blockIdx.x * blockDim.x + threadIdx.x;
    if (idx >= NPADW * Kpad) return;
    int n = idx / Kpad, k = idx - n * Kpad;
    out[idx] = (n < GN && k < K) ? tf32r(W[(size_t)n * ldW + colOff + k]) : 0.f;
}

// ------- gather + segment-sum over fp16 H rows, emits tf32 fp32 A ----------
__device__ __forceinline__ void acc8(float* a, uint4 u) {
    float2 f;
    f = __half22float2(*(__half2*)&u.x); a[0] += f.x; a[1] += f.y;
    f = __half22float2(*(__half2*)&u.y); a[2] += f.x; a[3] += f.y;
    f = __half22float2(*(__half2*)&u.z); a[4] += f.x; a[5] += f.y;
    f = __half22float2(*(__half2*)&u.w); a[6] += f.x; a[7] += f.y;
}
__device__ __forceinline__ float4 roundq(const float* a) {
    float4 r;
    r.x = tf32r(a[0]); r.y = tf32r(a[1]); r.z = tf32r(a[2]); r.w = tf32r(a[3]);
    return r;
}

__global__ __launch_bounds__(256) void seg_sum_k() {
    int gw = (blockIdx.x * blockDim.x + threadIdx.x) >> 5;
    int lane = threadIdx.x & 31;
    if (gw >= N_NODES) return;
    int beg = g_rowptr[gw], end = g_rowptr[gw + 1];
    bool hi = lane < 8;                       // uint4 idx 32..39
    float a0[8] = {}, a1[8] = {};

    int i = beg;
    // 4-edge unroll: issue all loads before any accumulation
    for (; i + 3 < end; i += 4) {
        const uint4* r0 = (const uint4*)(g_Hh + (size_t)g_csr[i]     * KH2);
        const uint4* r1 = (const uint4*)(g_Hh + (size_t)g_csr[i + 1] * KH2);
        const uint4* r2 = (const uint4*)(g_Hh + (size_t)g_csr[i + 2] * KH2);
        const uint4* r3 = (const uint4*)(g_Hh + (size_t)g_csr[i + 3] * KH2);
        uint4 x0 = __ldg(&r0[lane]), x1 = __ldg(&r1[lane]);
        uint4 x2 = __ldg(&r2[lane]), x3 = __ldg(&r3[lane]);
        uint4 y0, y1, y2, y3;
        if (hi) {
            y0 = __ldg(&r0[32 + lane]); y1 = __ldg(&r1[32 + lane]);
            y2 = __ldg(&r2[32 + lane]); y3 = __ldg(&r3[32 + lane]);
        }
        acc8(a0, x0); acc8(a0, x1); acc8(a0, x2); acc8(a0, x3);
        if (hi) { acc8(a1, y0); acc8(a1, y1); acc8(a1, y2); acc8(a1, y3); }
    }
    for (; i < end; i++) {
        const uint4* r0 = (const uint4*)(g_Hh + (size_t)g_csr[i] * KH2);
        uint4 x0 = __ldg(&r0[lane]);
        if (hi) { uint4 x1 = __ldg(&r0[32 + lane]); acc8(a1, x1); }
        acc8(a0, x0);
    }

    float4* Av = (float4*)(g_A + (size_t)gw * KP_H);
    Av[lane * 2]     = roundq(a0);
    Av[lane * 2 + 1] = roundq(a0 + 4);
    if (hi) {
        Av[64 + lane * 2]     = roundq(a1);
        Av[64 + lane * 2 + 1] = roundq(a1 + 4);
    }
}

// ==== SIMT SGEMM (Cs, K=14) with fused fp16-H0 add -> Rs ====================
__global__ __launch_bounds__(256) void sgemm_k(
    const float* __restrict__ X, int K, int M,
    const float* __restrict__ W, int ldW, int colOff,
    const float* __restrict__ bias, const int* __restrict__ degv,
    const __half* __restrict__ addh, float* __restrict__ Out)
{
    __shared__ __align__(16) float As[8][128];
    __shared__ __align__(16) float Bs[8][128];
    int tid = threadIdx.x;
    int m0 = blockIdx.x * 128;
    int n0 = blockIdx.y * 128;
    int xr = tid >> 3, xc = tid & 7;
    int tx = tid & 15, ty = tid >> 4;
    int mA = ty * 4, mB = 64 + ty * 4;
    int nA = tx * 4, nB = 64 + tx * 4;
    float acc[8][8] = {};

    for (int k0 = 0; k0 < K; k0 += 8) {
#pragma unroll
        for (int i = 0; i < 4; i++) {
            int m = xr + i * 32;
            int gm = m0 + m, gk = k0 + xc;
            As[xc][m] = (gm < M && gk < K) ? X[(size_t)gm * K + gk] : 0.f;
        }
#pragma unroll
        for (int i = 0; i < 4; i++) {
            int n = xr + i * 32;
            int gn = n0 + n, gk = k0 + xc;
            Bs[xc][n] = (gn < GN && gk < K) ? W[(size_t)gn * ldW + colOff + gk] : 0.f;
        }
        __syncthreads();
#pragma unroll
        for (int k = 0; k < 8; k++) {
            float4 q0 = *(const float4*)&As[k][mA];
            float4 q1 = *(const float4*)&As[k][mB];
            float4 b0 = *(const float4*)&Bs[k][nA];
            float4 b1 = *(const float4*)&Bs[k][nB];
            float av[8] = {q0.x, q0.y, q0.z, q0.w, q1.x, q1.y, q1.z, q1.w};
            float bv[8] = {b0.x, b0.y, b0.z, b0.w, b1.x, b1.y, b1.z, b1.w};
#pragma unroll
            for (int i = 0; i < 8; i++)
#pragma unroll
                for (int j = 0; j < 8; j++)
                    acc[i][j] += av[i] * bv[j];
        }
        __syncthreads();
    }
#pragma unroll
    for (int i = 0; i < 8; i++) {
        int m = m0 + ((i < 4) ? (ty * 4 + i) : (64 + ty * 4 + (i - 4)));
        if (m >= M) continue;
        float degf = degv ? (float)degv[m] : 1.f;
#pragma unroll
        for (int j = 0; j < 8; j++) {
            int n = n0 + ((j < 4) ? (tx * 4 + j) : (64 + tx * 4 + (j - 4)));
            if (n >= GN) continue;
            float v = acc[i][j] + degf * bias[n];
            if (addh) v += __half2float(addh[(size_t)m * KH2 + n]);
            Out[(size_t)m * GN + n] = v;
        }
    }
}

// ========== TF32 HMMA GEMM: 128x64 tile, 3 CTAs/SM, 1 product/K ============
// Outputs: Out (f32, GN pitch) and/or OutH (fp16, KH2 pitch). Scalar epilogue.
__global__ void __launch_bounds__(256, 3) tgemm_k(
    const float* __restrict__ X, const float* __restrict__ W,
    int Kpad, int nchunks, int M,
    const float* __restrict__ bias, const float* __restrict__ add1,
    const float* __restrict__ add2, int relu,
    float* __restrict__ Out, __half* __restrict__ OutH)
{
    extern __shared__ __align__(16) char smem[];
    uint32_t sb = s2u(smem);
    int tid = threadIdx.x, wid = tid >> 5, lane = tid & 31;
    int wm = wid & 3, wn = wid >> 2;       // 4 x 2 warp grid, warp tile 32x32
    int m0 = blockIdx.x * 128, n0 = blockIdx.y * 64;

    size_t ldb = (size_t)Kpad * 4;
    const char* gptr[2];
    gptr[0] = (const char*)(X + (size_t)m0 * Kpad);
    gptr[1] = (const char*)(W + (size_t)n0 * Kpad);

    float acc[2][4][4] = {};

#define LOAD_STAGE(s, c)                                                       \
    do {                                                                       \
        uint32_t _base = sb + (uint32_t)(s) * STAGE_B;                         \
        _Pragma("unroll")                                                      \
        for (int _t = 0; _t < 6; _t++) {                                       \
            int _id = _t * 256 + tid;                                          \
            int _r = _id >> 3;               /* 0..191 */                      \
            int _q = _id & 7;                                                  \
            int _mat = _r >> 7;              /* 0=A, 1=B */                    \
            int _rl = _r & 127;                                                \
            uint32_t _so = _base + _r * ROWB + _q * 16;                        \
            const char* _g = gptr[_mat] + (size_t)_rl * ldb                    \
                             + (size_t)(c) * 128 + _q * 16;                    \
            CPA16(_so, _g);                                                    \
        }                                                                      \
    } while (0)

    LOAD_STAGE(0, 0);
    CP_COMMIT();

    int r8 = lane & 7, qd = lane >> 3;
    int qrow = ((qd >> 1) << 3) + r8;
    int qoff = qrow * ROWB + ((qd & 1) << 4);

    for (int i = 0; i < nchunks; i++) {
        if (i + 1 < nchunks) {
            LOAD_STAGE((i + 1) & 1, i + 1);
            CP_COMMIT();
            cp_wait<1>();
        } else {
            cp_wait<0>();
        }
        __syncthreads();
        uint32_t stb = sb + (uint32_t)(i & 1) * STAGE_B;
        uint32_t abase = stb + (wm * 32) * ROWB + qoff;
        uint32_t bbase = stb + B_OFF + (wn * 32) * ROWB + qoff;

#pragma unroll
        for (int ks = 0; ks < 4; ks++) {       // four 8-K sub-chunks
            uint32_t a[2][4], b[4][2];
#pragma unroll
            for (int mt = 0; mt < 2; mt++) {
                uint32_t r0, r1, r2, r3;
                LDSM_X4(r0, r1, r2, r3, abase + mt * 16 * ROWB + ks * 32);
                a[mt][0] = r0; a[mt][1] = r2;
                a[mt][2] = r1; a[mt][3] = r3;
            }
#pragma unroll
            for (int p = 0; p < 2; p++) {
                uint32_t r0, r1, r2, r3;
                LDSM_X4(r0, r1, r2, r3, bbase + p * 16 * ROWB + ks * 32);
                b[p * 2][0] = r0;     b[p * 2][1] = r1;
                b[p * 2 + 1][0] = r2; b[p * 2 + 1][1] = r3;
            }
#pragma unroll
            for (int mt = 0; mt < 2; mt++)
#pragma unroll
                for (int nt = 0; nt < 4; nt++)
                    MMATF32(acc[mt][nt], a[mt][0], a[mt][1], a[mt][2], a[mt][3],
                            b[nt][0], b[nt][1]);
        }
        __syncthreads();
    }
#undef LOAD_STAGE

    float* Ds = (float*)smem;          // 128 x 68 floats = 34816 B < TG_SMEM
    int g = lane >> 2, tg = lane & 3;
#pragma unroll
    for (int mt = 0; mt < 2; mt++)
#pragma unroll
        for (int nt = 0; nt < 4; nt++) {
            int row = wm * 32 + mt * 16 + g;
            int col = wn * 32 + nt * 8 + tg * 2;
            Ds[row * 68 + col]           = acc[mt][nt][0];
            Ds[row * 68 + col + 1]       = acc[mt][nt][1];
            Ds[(row + 8) * 68 + col]     = acc[mt][nt][2];
            Ds[(row + 8) * 68 + col + 1] = acc[mt][nt][3];
        }
    __syncthreads();

    int col = tid & 63, rh = tid >> 6;
    int n = n0 + col;
    bool nv = n < GN;
    float bv = (bias && nv) ? bias[n] : 0.f;
    for (int r = rh * 32; r < rh * 32 + 32; r++) {
        int gm = m0 + r;
        if (gm >= M) break;
        float v = 0.f;
        if (nv) {
            v = Ds[r * 68 + col] + bv;
            if (add1) v += add1[(size_t)gm * GN + n];
            if (add2) v += add2[(size_t)gm * GN + n];
            if (relu) v = fmaxf(v, 0.f);
            if (Out) Out[(size_t)gm * GN + n] = v;
        }
        if (OutH) OutH[(size_t)gm * KH2 + n] = __float2half(v);  // pads -> 0
    }
}

// ======================= host orchestration =================================
extern "C" void kernel_launch(void* const* d_in, const int* in_sizes, int n_in,
                              void* d_out, int out_size) {
    const float* V   = (const float*)d_in[0];
    const float* E   = (const float*)d_in[1];
    const void*  EI  = d_in[2];
    const float* W_i = (const float*)d_in[3];
    const float* b_i = (const float*)d_in[4];
    const float* W_h = (const float*)d_in[5];
    const float* b_h = (const float*)d_in[6];
    const float* W_o = (const float*)d_in[7];
    const float* b_o = (const float*)d_in[8];
    float* out = (float*)d_out;

    int nE = in_sizes[2] / 2;
    int M  = in_sizes[0] / D_V;   // 50000

    float *Cs, *Ps, *SE, *A, *Vr;
    float *Wi, *WoV, *WhH, *WoH;
    __half* Hh;
    int *deg;
    cudaGetSymbolAddress((void**)&Cs, g_Cs);
    cudaGetSymbolAddress((void**)&Ps, g_Ps);
    cudaGetSymbolAddress((void**)&SE, g_SE);
    cudaGetSymbolAddress((void**)&Hh, g_Hh);
    cudaGetSymbolAddress((void**)&A,  g_A);
    cudaGetSymbolAddress((void**)&Vr, g_V);
    cudaGetSymbolAddress((void**)&Wi, g_Wi);
    cudaGetSymbolAddress((void**)&WoV, g_WoV);
    cudaGetSymbolAddress((void**)&WhH, g_WhH);
    cudaGetSymbolAddress((void**)&WoH, g_WoH);
    cudaGetSymbolAddress((void**)&deg, g_deg);

    cudaFuncSetAttribute(tgemm_k, cudaFuncAttributeMaxDynamicSharedMemorySize, TG_SMEM);

    cudaStream_t st = 0;
    const int TB = 256;
    int zeroN = N_NODES * D_E;
    int NB = (N_NODES + 255) / 256;
    dim3 tgGrid((M + 127) / 128, 5);       // 5 x 64 = 320 cols
    dim3 gemmGrid((M + 127) / 128, 3);
    int segGrid = (N_NODES * 32 + TB - 1) / TB;

    // ---- launches 1-4: keep tgemm_k at position 4 for ncu visibility -------
    roundV_k<<<(M * (KP_V / 4) + TB - 1) / TB, TB, 0, st>>>(V, M);             // 1
    prepW_k<<<(NPADW * KP_V + TB - 1) / TB, TB, 0, st>>>(W_i, D_V, 0, D_V,
                                                          KP_V, Wi);          // 2
    prepW_k<<<(NPADW * KP_H + TB - 1) / TB, TB, 0, st>>>(W_h, D_H + D_E, 0, D_H,
                                                          KP_H, WhH);         // 3
    // H0 = relu(V W_i^T + b_i): fp16 only
    tgemm_k<<<tgGrid, 256, TG_SMEM, st>>>(Vr, Wi, KP_V, KP_V / 32, M,
                                          b_i, nullptr, nullptr, 1,
                                          nullptr, Hh);                       // 4 (profiled)

    // ---- remaining prep + graph build --------------------------------------
    prepW_k<<<(NPADW * KP_V + TB - 1) / TB, TB, 0, st>>>(W_o, D_V + D_H, 0, D_V,
                                                          KP_V, WoV);
    prepW_k<<<(NPADW * KP_H + TB - 1) / TB, TB, 0, st>>>(W_o, D_V + D_H, D_V, D_H,
                                                          KP_H, WoH);
    init_k<<<(zeroN + TB - 1) / TB, TB, 0, st>>>((const unsigned long long*)EI, nE);
    convert_hist_k<<<(nE + TB - 1) / TB, TB, 0, st>>>(EI, nE);
    scan1_k<<<NB, 256, 0, st>>>();
    scan2_k<<<1, 256, 0, st>>>(NB);
    scan3_k<<<NB, 256, 0, st>>>();
    csr_fill_k<<<(nE + TB - 1) / TB, TB, 0, st>>>(nE);
    se_scatter_k<<<(nE + TB - 1) / TB, TB, 0, st>>>(E, nE);

    // Ps = V @ W_oV^T + b_o
    tgemm_k<<<tgGrid, 256, TG_SMEM, st>>>(Vr, WoV, KP_V, KP_V / 32, M,
                                          b_o, nullptr, nullptr, 0, Ps, nullptr);
    // Rs (in Cs) = SE @ W_hE^T + deg * b_h + H0(fp16)   (SIMT, K=14)
    sgemm_k<<<gemmGrid, TB, 0, st>>>(SE, D_E, M, W_h, D_H + D_E, D_H, b_h, deg, Hh, Cs);

    // layer 1: Hh = fp16(relu(segsum(Hh[src]) @ W_hH^T + Rs))
    seg_sum_k<<<segGrid, TB, 0, st>>>();
    tgemm_k<<<tgGrid, 256, TG_SMEM, st>>>(A, WhH, KP_H, KP_H / 32, M,
                                          nullptr, Cs, nullptr, 1, nullptr, Hh);
    // layer 2
    seg_sum_k<<<segGrid, TB, 0, st>>>();
    tgemm_k<<<tgGrid, 256, TG_SMEM, st>>>(A, WhH, KP_H, KP_H / 32, M,
                                          nullptr, Cs, nullptr, 1, nullptr, Hh);
    // final: out = relu(Ps + segsum(Hh[src]) @ W_oH^T)
    seg_sum_k<<<segGrid, TB, 0, st>>>();
    tgemm_k<<<tgGrid, 256, TG_SMEM, st>>>(A, WoH, KP_H, KP_H / 32, M,
                                          nullptr, Ps, nullptr, 1, out, nullptr);
}